// round 14
// baseline (speedup 1.0000x reference)
#include <cuda_runtime.h>
#include <cuda_fp16.h>
#include <cstdint>
#include <cstring>

#define D_DIM   11008
#define K_DIM   172
#define NKB     11           // k16 blocks for GEMM-1 (j = 0..175)
#define BP      72           // Bs row pitch in uint32 (288B) — bank-verified
#define THREADS 128
#define SMEM_BYTES (88 * BP * 4)   // 25344

static __device__ __forceinline__ uint32_t h2_bits(__half2 h) {
    uint32_t u;
    memcpy(&u, &h, 4);
    return u;
}

// had_K * (1/sqrt(D)) pre-packed into fp16 m16n8k16 A-fragment order (R9 layout):
//   block (mw, t, kb) -> 32 lanes -> uint4 {a0, a1, a2, a3}, one LDG.128 per (t,kb).
__device__ uint4 g_hKh[4 * 3 * NKB * 32];

__global__ void prep_hk(const float* __restrict__ hK) {
    int idx = blockIdx.x * blockDim.x + threadIdx.x;
    if (idx >= 4 * 3 * NKB * 32) return;
    int lane = idx & 31;
    int kb   = (idx >> 5) % NKB;
    int t    = (idx >> 5) / NKB % 3;
    int mw   = (idx >> 5) / (NKB * 3);
    int q = lane >> 2, p = lane & 3;
    int i  = mw * 48 + t * 16 + q;
    int k0 = 16 * kb + 2 * p;
    const float scale = rsqrtf((float)D_DIM);   // fold 1/sqrt(D) into hK
    float f[8];
    #pragma unroll
    for (int e = 0; e < 8; ++e) {
        int ii = i + ((e >> 1) & 1) * 8;
        int kk = k0 + (e >> 2) * 8 + (e & 1);
        f[e] = (ii < K_DIM && kk < K_DIM) ? hK[ii * K_DIM + kk] * scale : 0.f;
    }
    uint4 r;
    r.x = h2_bits(__floats2half2_rn(f[0], f[1]));
    r.y = h2_bits(__floats2half2_rn(f[2], f[3]));
    r.z = h2_bits(__floats2half2_rn(f[4], f[5]));
    r.w = h2_bits(__floats2half2_rn(f[6], f[7]));
    g_hKh[idx] = r;
}

__global__ __launch_bounds__(THREADS, 4)
void had_mma_kernel(const float* __restrict__ x,
                    float* __restrict__ out)
{
    extern __shared__ uint32_t Bs[];   // [88][BP] half2 pair-packed Xr
    const int tid  = threadIdx.x;
    const int w    = tid >> 5;               // 0..3 (= mw, M-tile)
    const int lane = tid & 31;
    const int q    = lane >> 2;              // 0..7
    const int p    = lane & 3;               // 0..3
    const int row  = blockIdx.x;

    // H_64 fragment constants (Sylvester, R11-validated): hA or hA^signflip.
    const uint32_t pq = (uint32_t)(__popc(p & (q >> 1)) & 1);
    const uint32_t t0 = (uint32_t)(q & 1);
    const uint32_t hA  = 0x3C003C00u | (pq << 15) | ((pq ^ t0) << 31);
    const uint32_t hAf = hA ^ 0x80008000u;

    // ---------- Phase 1: float4 bulk load -> half2 pair-packed Bs (R13-proven) ----------
    {
        const float* xr = x + (size_t)row * D_DIM;
        const int s  = lane >> 4;            // 0..1
        const int mg = lane & 15;            // m/4 group
        #pragma unroll
        for (int k2 = 0; k2 < 11; ++k2) {
            const int c2 = 2 * w + s + 8 * k2;
            float4 lo = make_float4(0.f, 0.f, 0.f, 0.f);
            float4 hi = lo;
            if (c2 < 86) {
                const float* bp = xr + (size_t)c2 * 128 + 4 * mg;
                lo = *(const float4*)(bp);
                hi = *(const float4*)(bp + 64);
            }
            uint4 pk;
            pk.x = h2_bits(__floats2half2_rn(lo.x, hi.x));
            pk.y = h2_bits(__floats2half2_rn(lo.y, hi.y));
            pk.z = h2_bits(__floats2half2_rn(lo.z, hi.z));
            pk.w = h2_bits(__floats2half2_rn(lo.w, hi.w));
            *(uint4*)(Bs + c2 * BP + 4 * mg) = pk;
        }
    }
    __syncthreads();

    // ---------- Phase 2: T = (hK/sqrtD) @ Xr via m16n8k16 fp16 (4M x 1N warps) ----------
    float acc[3][8][4];
    #pragma unroll
    for (int t = 0; t < 3; ++t)
        #pragma unroll
        for (int u = 0; u < 8; ++u)
            #pragma unroll
            for (int e = 0; e < 4; ++e) acc[t][u][e] = 0.f;

    const uint4* Aw = g_hKh + (size_t)(w * 3) * NKB * 32 + lane;

    #pragma unroll 2
    for (int kb = 0; kb < NKB; ++kb) {
        uint32_t b0[8], b1[8];
        const uint32_t* br = Bs + (8 * kb + p) * BP + q;
        #pragma unroll
        for (int u = 0; u < 8; ++u) {
            b0[u] = br[8 * u];                // k = 16kb+2p, +1
            b1[u] = br[8 * u + 4 * BP];       // k = 16kb+2p+8, +9
        }
        #pragma unroll
        for (int t = 0; t < 3; ++t) {
            uint4 a = Aw[(size_t)(t * NKB + kb) * 32];   // one coalesced LDG.128
            #pragma unroll
            for (int u = 0; u < 8; ++u) {
                asm volatile(
                    "mma.sync.aligned.m16n8k16.row.col.f32.f16.f16.f32 "
                    "{%0,%1,%2,%3}, {%4,%5,%6,%7}, {%8,%9}, {%0,%1,%2,%3};"
                    : "+f"(acc[t][u][0]), "+f"(acc[t][u][1]),
                      "+f"(acc[t][u][2]), "+f"(acc[t][u][3])
                    : "r"(a.x), "r"(a.y), "r"(a.z), "r"(a.w),
                      "r"(b0[u]), "r"(b1[u]));
            }
        }
    }

    // ---------- Phase 3: out = T @ H_64 (pack-then-free, u-halves for low reg peak) ----------
    {
        float* orow = out + (size_t)row * D_DIM;
        const int i0 = w * 48;
        #pragma unroll
        for (int t = 0; t < 3; ++t) {
            // pack acc[t] into 16 fragment regs; acc[t] floats die here
            uint32_t af[4][4];
            #pragma unroll
            for (int v = 0; v < 4; ++v) {
                af[v][0] = h2_bits(__floats2half2_rn(acc[t][2*v  ][0], acc[t][2*v  ][1]));
                af[v][1] = h2_bits(__floats2half2_rn(acc[t][2*v  ][2], acc[t][2*v  ][3]));
                af[v][2] = h2_bits(__floats2half2_rn(acc[t][2*v+1][0], acc[t][2*v+1][1]));
                af[v][3] = h2_bits(__floats2half2_rn(acc[t][2*v+1][2], acc[t][2*v+1][3]));
            }
            const int ib = i0 + t * 16 + q;
            #pragma unroll
            for (int uh = 0; uh < 2; ++uh) {
                float a2c[4][4];
                #pragma unroll
                for (int du = 0; du < 4; ++du)
                    #pragma unroll
                    for (int e = 0; e < 4; ++e) a2c[du][e] = 0.f;

                #pragma unroll
                for (int v = 0; v < 4; ++v) {
                    #pragma unroll
                    for (int du = 0; du < 4; ++du) {
                        const int u = uh * 4 + du;
                        // sign flips (R11-validated)
                        const int c0s = (((v & 1) & ((u >> 1) & 1)) ^ (((v >> 1) & 1) & ((u >> 2) & 1)));
                        const int c1s = c0s ^ (u & 1);
                        const uint32_t hb0 = c0s ? hAf : hA;
                        const uint32_t hb1 = c1s ? hAf : hA;
                        asm volatile(
                            "mma.sync.aligned.m16n8k16.row.col.f32.f16.f16.f32 "
                            "{%0,%1,%2,%3}, {%4,%5,%6,%7}, {%8,%9}, {%0,%1,%2,%3};"
                            : "+f"(a2c[du][0]), "+f"(a2c[du][1]),
                              "+f"(a2c[du][2]), "+f"(a2c[du][3])
                            : "r"(af[v][0]), "r"(af[v][1]), "r"(af[v][2]), "r"(af[v][3]),
                              "r"(hb0), "r"(hb1));
                    }
                }
                // direct store of this u-half (8-row x 32B runs)
                #pragma unroll
                for (int du = 0; du < 4; ++du) {
                    const int m = (uh * 4 + du) * 8 + 2 * p;
                    if (ib < K_DIM)
                        *(float2*)(orow + ib * 64 + m) = make_float2(a2c[du][0], a2c[du][1]);
                    if (ib + 8 < K_DIM)
                        *(float2*)(orow + (ib + 8) * 64 + m) = make_float2(a2c[du][2], a2c[du][3]);
                }
            }
        }
    }
}

extern "C" void kernel_launch(void* const* d_in, const int* in_sizes, int n_in,
                              void* d_out, int out_size)
{
    const float* x  = (const float*)d_in[0];
    const float* hK = (const float*)d_in[1];
    int nx = in_sizes[0];
    if (n_in > 1 && in_sizes[0] == K_DIM * K_DIM) {   // defensive input-order check
        x  = (const float*)d_in[1];
        hK = (const float*)d_in[0];
        nx = in_sizes[1];
    }
    float* out = (float*)d_out;
    const int nrows = nx / D_DIM;

    cudaFuncSetAttribute(had_mma_kernel,
                         cudaFuncAttributeMaxDynamicSharedMemorySize, SMEM_BYTES);

    prep_hk<<<(4 * 3 * NKB * 32 + 255) / 256, 256>>>(hK);
    had_mma_kernel<<<nrows, THREADS, SMEM_BYTES>>>(x, out);
}

// round 15
// speedup vs baseline: 1.2186x; 1.2186x over previous
#include <cuda_runtime.h>
#include <cuda_fp16.h>
#include <cstdint>
#include <cstring>

#define D_DIM   11008
#define K_DIM   172
#define NKB     11           // k16 blocks for GEMM-1 (j = 0..175)
#define BP      72           // Bs row pitch in uint32 (288B) — bank-verified
#define THREADS 128
#define BSZ     (88 * BP)    // one row buffer (uint32s)
#define SMEM_BYTES (2 * BSZ * 4)   // 50688

static __device__ __forceinline__ uint32_t h2_bits(__half2 h) {
    uint32_t u;
    memcpy(&u, &h, 4);
    return u;
}

// had_K * (1/sqrt(D)) pre-packed into fp16 m16n8k16 A-fragment order (R9 layout):
//   block (mw, t, kb) -> 32 lanes -> uint4 {a0, a1, a2, a3}, one LDG.128 per (t,kb).
__device__ uint4 g_hKh[4 * 3 * NKB * 32];

__global__ void prep_hk(const float* __restrict__ hK) {
    int idx = blockIdx.x * blockDim.x + threadIdx.x;
    if (idx >= 4 * 3 * NKB * 32) return;
    int lane = idx & 31;
    int kb   = (idx >> 5) % NKB;
    int t    = (idx >> 5) / NKB % 3;
    int mw   = (idx >> 5) / (NKB * 3);
    int q = lane >> 2, p = lane & 3;
    int i  = mw * 48 + t * 16 + q;
    int k0 = 16 * kb + 2 * p;
    const float scale = rsqrtf((float)D_DIM);   // fold 1/sqrt(D) into hK
    float f[8];
    #pragma unroll
    for (int e = 0; e < 8; ++e) {
        int ii = i + ((e >> 1) & 1) * 8;
        int kk = k0 + (e >> 2) * 8 + (e & 1);
        f[e] = (ii < K_DIM && kk < K_DIM) ? hK[ii * K_DIM + kk] * scale : 0.f;
    }
    uint4 r;
    r.x = h2_bits(__floats2half2_rn(f[0], f[1]));
    r.y = h2_bits(__floats2half2_rn(f[2], f[3]));
    r.z = h2_bits(__floats2half2_rn(f[4], f[5]));
    r.w = h2_bits(__floats2half2_rn(f[6], f[7]));
    g_hKh[idx] = r;
}

__global__ __launch_bounds__(THREADS, 3)
void had_mma_kernel(const float* __restrict__ x,
                    float* __restrict__ out,
                    int nrows)
{
    extern __shared__ uint32_t Bs[];   // 2 x [88][BP] half2 pair-packed Xr
    const int tid  = threadIdx.x;
    const int w    = tid >> 5;               // 0..3 (= mw, M-tile)
    const int lane = tid & 31;
    const int q    = lane >> 2;              // 0..7
    const int p    = lane & 3;               // 0..3
    const int row0 = blockIdx.x * 2;

    // H_64 fragment constants (Sylvester, R11-validated): hA or hA^signflip.
    const uint32_t pq = (uint32_t)(__popc(p & (q >> 1)) & 1);
    const uint32_t t0 = (uint32_t)(q & 1);
    const uint32_t hA  = 0x3C003C00u | (pq << 15) | ((pq ^ t0) << 31);
    const uint32_t hAf = hA ^ 0x80008000u;

    // ---------- Phase 1: float4 bulk load BOTH rows -> Bs (44 LDG.128 in flight) ----------
    {
        const int s  = lane >> 4;            // 0..1
        const int mg = lane & 15;            // m/4 group
        const int nr = (nrows - row0 >= 2) ? 2 : (nrows - row0);
        for (int rr = 0; rr < nr; ++rr) {
            const float* xr = x + (size_t)(row0 + rr) * D_DIM;
            uint32_t* Bb = Bs + rr * BSZ;
            #pragma unroll
            for (int k2 = 0; k2 < 11; ++k2) {
                const int c2 = 2 * w + s + 8 * k2;
                float4 lo = make_float4(0.f, 0.f, 0.f, 0.f);
                float4 hi = lo;
                if (c2 < 86) {
                    const float* bp = xr + (size_t)c2 * 128 + 4 * mg;
                    lo = *(const float4*)(bp);
                    hi = *(const float4*)(bp + 64);
                }
                uint4 pk;
                pk.x = h2_bits(__floats2half2_rn(lo.x, hi.x));
                pk.y = h2_bits(__floats2half2_rn(lo.y, hi.y));
                pk.z = h2_bits(__floats2half2_rn(lo.z, hi.z));
                pk.w = h2_bits(__floats2half2_rn(lo.w, hi.w));
                *(uint4*)(Bb + c2 * BP + 4 * mg) = pk;
            }
        }
    }
    __syncthreads();

    // ---------- Rows: GEMM-1 -> GEMM-2 -> store (row0 STGs overlap row1 GEMM-1) ----------
    #pragma unroll 1
    for (int rr = 0; rr < 2; ++rr) {
        const int row = row0 + rr;
        if (row >= nrows) break;
        const uint32_t* Bc = Bs + rr * BSZ;

        // ---- GEMM-1: T = (hK/sqrtD) @ Xr via m16n8k16 fp16 (4M x 1N warps) ----
        float acc[3][8][4];
        #pragma unroll
        for (int t = 0; t < 3; ++t)
            #pragma unroll
            for (int u = 0; u < 8; ++u)
                #pragma unroll
                for (int e = 0; e < 4; ++e) acc[t][u][e] = 0.f;

        const uint4* Aw = g_hKh + (size_t)(w * 3) * NKB * 32 + lane;

        #pragma unroll 2
        for (int kb = 0; kb < NKB; ++kb) {
            uint32_t b0[8], b1[8];
            const uint32_t* br = Bc + (8 * kb + p) * BP + q;
            #pragma unroll
            for (int u = 0; u < 8; ++u) {
                b0[u] = br[8 * u];                // k = 16kb+2p, +1
                b1[u] = br[8 * u + 4 * BP];       // k = 16kb+2p+8, +9
            }
            #pragma unroll
            for (int t = 0; t < 3; ++t) {
                uint4 a = Aw[(size_t)(t * NKB + kb) * 32];   // one coalesced LDG.128
                #pragma unroll
                for (int u = 0; u < 8; ++u) {
                    asm volatile(
                        "mma.sync.aligned.m16n8k16.row.col.f32.f16.f16.f32 "
                        "{%0,%1,%2,%3}, {%4,%5,%6,%7}, {%8,%9}, {%0,%1,%2,%3};"
                        : "+f"(acc[t][u][0]), "+f"(acc[t][u][1]),
                          "+f"(acc[t][u][2]), "+f"(acc[t][u][3])
                        : "r"(a.x), "r"(a.y), "r"(a.z), "r"(a.w),
                          "r"(b0[u]), "r"(b1[u]));
                }
            }
        }

        // ---- GEMM-2: out = T @ H_64 (A register-direct, H from 2 registers) ----
        {
            float* orow = out + (size_t)row * D_DIM;
            const int i0 = w * 48;
            #pragma unroll
            for (int t = 0; t < 3; ++t) {
                float a2c[8][4];
                #pragma unroll
                for (int u = 0; u < 8; ++u)
                    #pragma unroll
                    for (int e = 0; e < 4; ++e) a2c[u][e] = 0.f;

                #pragma unroll
                for (int v = 0; v < 4; ++v) {
                    const uint32_t a0 = h2_bits(__floats2half2_rn(acc[t][2*v  ][0], acc[t][2*v  ][1]));
                    const uint32_t a1 = h2_bits(__floats2half2_rn(acc[t][2*v  ][2], acc[t][2*v  ][3]));
                    const uint32_t a2 = h2_bits(__floats2half2_rn(acc[t][2*v+1][0], acc[t][2*v+1][1]));
                    const uint32_t a3 = h2_bits(__floats2half2_rn(acc[t][2*v+1][2], acc[t][2*v+1][3]));
                    #pragma unroll
                    for (int u = 0; u < 8; ++u) {
                        // sign flips (R11-validated)
                        const int c0s = (((v & 1) & ((u >> 1) & 1)) ^ (((v >> 1) & 1) & ((u >> 2) & 1)));
                        const int c1s = c0s ^ (u & 1);
                        const uint32_t hb0 = c0s ? hAf : hA;
                        const uint32_t hb1 = c1s ? hAf : hA;
                        asm volatile(
                            "mma.sync.aligned.m16n8k16.row.col.f32.f16.f16.f32 "
                            "{%0,%1,%2,%3}, {%4,%5,%6,%7}, {%8,%9}, {%0,%1,%2,%3};"
                            : "+f"(a2c[u][0]), "+f"(a2c[u][1]),
                              "+f"(a2c[u][2]), "+f"(a2c[u][3])
                            : "r"(a0), "r"(a1), "r"(a2), "r"(a3),
                              "r"(hb0), "r"(hb1));
                    }
                }
                // direct store (8-row x 32B runs)
                const int ib = i0 + t * 16 + q;
                #pragma unroll
                for (int u = 0; u < 8; ++u) {
                    const int m = u * 8 + 2 * p;
                    if (ib < K_DIM)
                        *(float2*)(orow + ib * 64 + m) = make_float2(a2c[u][0], a2c[u][1]);
                    if (ib + 8 < K_DIM)
                        *(float2*)(orow + (ib + 8) * 64 + m) = make_float2(a2c[u][2], a2c[u][3]);
                }
            }
        }
    }
}

extern "C" void kernel_launch(void* const* d_in, const int* in_sizes, int n_in,
                              void* d_out, int out_size)
{
    const float* x  = (const float*)d_in[0];
    const float* hK = (const float*)d_in[1];
    int nx = in_sizes[0];
    if (n_in > 1 && in_sizes[0] == K_DIM * K_DIM) {   // defensive input-order check
        x  = (const float*)d_in[1];
        hK = (const float*)d_in[0];
        nx = in_sizes[1];
    }
    float* out = (float*)d_out;
    const int nrows = nx / D_DIM;
    const int grid  = (nrows + 1) / 2;

    cudaFuncSetAttribute(had_mma_kernel,
                         cudaFuncAttributeMaxDynamicSharedMemorySize, SMEM_BYTES);

    prep_hk<<<(4 * 3 * NKB * 32 + 255) / 256, 256>>>(hK);
    had_mma_kernel<<<grid, THREADS, SMEM_BYTES>>>(x, out, nrows);
}